// round 6
// baseline (speedup 1.0000x reference)
#include <cuda_runtime.h>
#include <cstdint>

// LatentDT: z[n,v] = clamp(min over edges on root->v path of +-(x[n].A[s]), 0, 1)
// Pruned DFS visits ~DEPTH+1 splits per row; kernel is output-store bound.
//
// R6: stage 4 output rows per block in SMEM, emit ONE TMA bulk store
// (cp.async.bulk) per block -> no STG wavefronts through L1/LSU at all.

#define DEPTH     10
#define NB_SPLIT  1023   // 2^10 - 1
#define NB_NODES  2047   // 2^11 - 1
#define KDIM      128

#define ROWS_PER_BLOCK 4
#define THREADS        128
#define BLOCK_FLOATS   (ROWS_PER_BLOCK * NB_NODES)   // 8188 floats
#define BLOCK_BYTES    (BLOCK_FLOATS * 4)            // 32752 B, multiple of 16

__device__ __forceinline__ uint32_t smem_u32(const void* p) {
    uint32_t a;
    asm("{ .reg .u64 t; cvta.to.shared.u64 t, %1; cvt.u32.u64 %0, t; }"
        : "=r"(a) : "l"(p));
    return a;
}

__global__ void __launch_bounds__(THREADS) latentdt_kernel(
    const float* __restrict__ x,
    const float* __restrict__ A,
    float* __restrict__ out,
    int rows)
{
    __shared__ __align__(128) float srow[BLOCK_FLOATS];

    const int tid  = threadIdx.x;
    const int lane = tid & 31;
    const int warp = tid >> 5;
    const int row0 = blockIdx.x * ROWS_PER_BLOCK;
    const int row  = row0 + warp;

    // ---- Cooperative SMEM zero: 8188 floats = 2047 uint4 exactly ----
    {
        float4* s4 = reinterpret_cast<float4*>(srow);
        const float4 z4 = make_float4(0.f, 0.f, 0.f, 0.f);
        #pragma unroll 4
        for (int i = tid; i < BLOCK_FLOATS / 4; i += THREADS) s4[i] = z4;
    }
    __syncthreads();

    if (row < rows) {
        // x row: 128 floats, 4 per lane.
        const float4 xv = __ldg(reinterpret_cast<const float4*>(
                                    x + (size_t)row * KDIM) + lane);
        float* sr = srow + warp * NB_NODES;
        if (lane == 0) sr[0] = 1.0f;          // root: clamp(1) = 1

        // ---- Warp-uniform lazy DFS, scatter into SMEM ----
        int   st_node[DEPTH + 1];
        float st_q[DEPTH + 1];
        int   sp   = 0;
        int   node = 0;
        float q    = 1.0f;

        while (true) {
            const float4 av = __ldg(reinterpret_cast<const float4*>(
                                        A + (size_t)node * KDIM) + lane);
            float p = fmaf(xv.x, av.x,
                      fmaf(xv.y, av.y,
                      fmaf(xv.z, av.z, xv.w * av.w)));
            p += __shfl_xor_sync(0xffffffffu, p, 16);
            p += __shfl_xor_sync(0xffffffffu, p, 8);
            p += __shfl_xor_sync(0xffffffffu, p, 4);
            p += __shfl_xor_sync(0xffffffffu, p, 2);
            p += __shfl_xor_sync(0xffffffffu, p, 1);
            // p is warp-uniform.

            const float qL = fminf(q, p);     // <= 1 always
            const float qR = fminf(q, -p);
            const int cl = 2 * node + 1;

            if (lane == 0) {
                if (qL > 0.0f) sr[cl]     = qL;
                if (qR > 0.0f) sr[cl + 1] = qR;
            }

            const bool childIsSplit = (cl < NB_SPLIT);
            const bool goL = childIsSplit && (qL > 0.0f);
            const bool goR = childIsSplit && (qR > 0.0f);

            if (goL) {
                if (goR) { st_node[sp] = cl + 1; st_q[sp] = qR; ++sp; }
                node = cl;  q = qL;
            } else if (goR) {
                node = cl + 1;  q = qR;
            } else {
                if (sp == 0) break;
                --sp;
                node = st_node[sp];  q = st_q[sp];
            }
        }
    }
    __syncthreads();

    // ---- One TMA bulk store per block: SMEM -> GMEM, no STG path ----
    if (row0 + ROWS_PER_BLOCK <= rows) {
        if (tid == 0) {
            float* gdst = out + (size_t)row0 * NB_NODES;   // 16B-aligned: 32752*blockIdx
            const uint32_t saddr = smem_u32(srow);
            asm volatile("fence.proxy.async.shared::cta;" ::: "memory");
            asm volatile(
                "cp.async.bulk.global.shared::cta.bulk_group [%0], [%1], %2;"
                :: "l"(gdst), "r"(saddr), "n"(BLOCK_BYTES) : "memory");
            asm volatile("cp.async.bulk.commit_group;" ::: "memory");
            asm volatile("cp.async.bulk.wait_group 0;" ::: "memory");
        }
    } else {
        // Tail block (rows % 4 != 0 only): plain coalesced stores.
        const size_t base  = (size_t)row0 * NB_NODES;
        const size_t total = (size_t)rows * NB_NODES;
        for (size_t i = base + tid; i < total; i += THREADS)
            out[i] = srow[i - base];
    }
}

extern "C" void kernel_launch(void* const* d_in, const int* in_sizes, int n_in,
                              void* d_out, int out_size)
{
    const float* x = (const float*)d_in[0];   // [rows, 128]
    const float* A = (const float*)d_in[1];   // [1023, 128]
    float* out = (float*)d_out;               // [rows, 2047]

    const int rows = out_size / NB_NODES;     // 32768

    const int blocks = (rows + ROWS_PER_BLOCK - 1) / ROWS_PER_BLOCK;
    latentdt_kernel<<<blocks, THREADS>>>(x, A, out, rows);
}